// round 4
// baseline (speedup 1.0000x reference)
#include <cuda_runtime.h>
#include <cuda_bf16.h>
#include <cstdint>
#include <cstddef>

#define N_PTS 8192
#define DIMS  128
#define KNBR  14

#define SM_STRIDE 136   // bf16 stride for A/B tiles (128 + 8 pad)
#define SC_STRIDE 132   // f32 stride for score tile (conflict-free scan)

// ---------------- scratch ----------------
__device__ __align__(16) __nv_bfloat16 g_XB[N_PTS * DIMS];   // 2 MB bf16 copy of X (L2-resident)
__device__ float  g_SQ[N_PTS];
__device__ int    g_NBR[N_PTS * KNBR];
__device__ double g_partial_bulk[512];
__device__ double g_partial_corr[1024];

// ---------------- fast-math ----------------
__device__ __forceinline__ float f_sqrt(float x){ float r; asm("sqrt.approx.f32 %0, %1;" : "=f"(r) : "f"(x)); return r; }
__device__ __forceinline__ float f_rcp (float x){ float r; asm("rcp.approx.f32 %0, %1;"  : "=f"(r) : "f"(x)); return r; }
__device__ __forceinline__ float f_lg2 (float x){ float r; asm("lg2.approx.f32 %0, %1;"  : "=f"(r) : "f"(x)); return r; }
__device__ __forceinline__ float f_ex2 (float x){ float r; asm("ex2.approx.f32 %0, %1;"  : "=f"(r) : "f"(x)); return r; }

#define LN2F 0.69314718055994531f
#define LOG2EF 1.4426950408889634f

__device__ __forceinline__ void cp_async16(uint32_t dst, const void* src) {
    asm volatile("cp.async.cg.shared.global [%0], [%1], 16;" :: "r"(dst), "l"(src));
}

__device__ __forceinline__ void mma16816(float* c, const uint32_t* a, const uint32_t* b) {
    asm volatile(
        "mma.sync.aligned.m16n8k16.row.col.f32.bf16.bf16.f32 "
        "{%0,%1,%2,%3}, {%4,%5,%6,%7}, {%8,%9}, {%0,%1,%2,%3};"
        : "+f"(c[0]), "+f"(c[1]), "+f"(c[2]), "+f"(c[3])
        : "r"(a[0]), "r"(a[1]), "r"(a[2]), "r"(a[3]), "r"(b[0]), "r"(b[1]));
}

// ---------------- 1) prep: bf16 convert + row norms ----------------
__global__ void prep_kernel(const float* __restrict__ X) {
    int warp = threadIdx.x >> 5, lane = threadIdx.x & 31;
    int row  = blockIdx.x * 8 + warp;
    const float* xr = X + (size_t)row * DIMS;
    float v0 = xr[lane], v1 = xr[lane + 32], v2 = xr[lane + 64], v3 = xr[lane + 96];
    __nv_bfloat16* xb = g_XB + (size_t)row * DIMS;
    xb[lane]      = __float2bfloat16(v0);
    xb[lane + 32] = __float2bfloat16(v1);
    xb[lane + 64] = __float2bfloat16(v2);
    xb[lane + 96] = __float2bfloat16(v3);
    float s = v0*v0 + v1*v1 + v2*v2 + v3*v3;
    #pragma unroll
    for (int off = 16; off; off >>= 1) s += __shfl_xor_sync(0xffffffffu, s, off);
    if (lane == 0) g_SQ[row] = s;
}

// ---------------- 2) fused GEMM + top-14 (no gmem scratch) ----------------
// Block: 256 threads, owns 64 rows; loops 64 col tiles of 128.
// smem: sA 64x136 bf16 | sB 2x 128x136 bf16 | sSQ 8192 f32 | sScore 64x132 f32
#define SMEM_A_BYTES   (64 * SM_STRIDE * 2)            // 17408
#define SMEM_B_BYTES   (128 * SM_STRIDE * 2)           // 34816 per buffer
#define SMEM_FUSED_TOTAL (SMEM_A_BYTES + 2*SMEM_B_BYTES + N_PTS*4 + 64*SC_STRIDE*4)  // 153600

__global__ __launch_bounds__(256, 1) void fused_gemm_topk() {
    extern __shared__ __align__(16) char smem_raw[];
    __nv_bfloat16* sA  = (__nv_bfloat16*)smem_raw;
    __nv_bfloat16* sB  = sA + 64 * SM_STRIDE;                 // 2 buffers
    float*         sSQ = (float*)(sB + 2 * 128 * SM_STRIDE);
    float*         sSc = sSQ + N_PTS;

    int tid = threadIdx.x;
    int rowBlk = blockIdx.x * 64;

    uint32_t sA_u = (uint32_t)__cvta_generic_to_shared(sA);
    uint32_t sB_u = (uint32_t)__cvta_generic_to_shared(sB);

    // full sq vector (32 KB) - plain loads
    {
        const float4* src = (const float4*)g_SQ;
        float4* dst = (float4*)sSQ;
        #pragma unroll
        for (int i = 0; i < 8; i++) dst[tid + i * 256] = src[tid + i * 256];
    }
    // A tile (64x128) via cp.async
    #pragma unroll
    for (int i = 0; i < 4; i++) {
        int c = tid + i * 256;
        int r = c >> 4, q = c & 15;
        cp_async16(sA_u + (uint32_t)(r * SM_STRIDE + q * 8) * 2,
                   g_XB + (size_t)(rowBlk + r) * DIMS + q * 8);
    }
    // B tile 0
    #pragma unroll
    for (int i = 0; i < 8; i++) {
        int c = tid + i * 256;
        int r = c >> 4, q = c & 15;
        cp_async16(sB_u + (uint32_t)(r * SM_STRIDE + q * 8) * 2,
                   g_XB + (size_t)r * DIMS + q * 8);
    }
    asm volatile("cp.async.commit_group;");

    int warp = tid >> 5, lane = tid & 31;
    int wm = warp & 1, wn = warp >> 1;       // 2x4 warp grid, 32x32 per warp
    int grp = lane >> 2, tig = lane & 3;

    // per-thread running top-14 over this thread's scan lanes
    float bk[KNBR]; int bi[KNBR];
    #pragma unroll
    for (int s = 0; s < KNBR; s++) { bk[s] = -3.4e38f; bi[s] = 0x7fffffff; }

    int srow = tid & 63, seg = tid >> 6;     // scan mapping: 4 threads per row

    for (int t = 0; t < N_PTS / 128; t++) {
        int buf = t & 1;
        if (t + 1 < N_PTS / 128) {
            uint32_t bdst = sB_u + (uint32_t)((1 - buf) * 128 * SM_STRIDE) * 2;
            const __nv_bfloat16* bsrc = g_XB + (size_t)(t + 1) * 128 * DIMS;
            #pragma unroll
            for (int i = 0; i < 8; i++) {
                int c = tid + i * 256;
                int r = c >> 4, q = c & 15;
                cp_async16(bdst + (uint32_t)(r * SM_STRIDE + q * 8) * 2,
                           bsrc + (size_t)r * DIMS + q * 8);
            }
            asm volatile("cp.async.commit_group;");
            asm volatile("cp.async.wait_group 1;");
        } else {
            asm volatile("cp.async.wait_group 0;");
        }
        __syncthreads();

        // ---- MMA: 64x128 tile ----
        float acc[2][4][4];
        #pragma unroll
        for (int mt = 0; mt < 2; mt++)
            #pragma unroll
            for (int nt = 0; nt < 4; nt++)
                #pragma unroll
                for (int q = 0; q < 4; q++) acc[mt][nt][q] = 0.f;

        const __nv_bfloat16* pA = sA + (wm * 32) * SM_STRIDE;
        const __nv_bfloat16* pB = sB + (size_t)buf * 128 * SM_STRIDE + (wn * 32) * SM_STRIDE;

        #pragma unroll
        for (int kk = 0; kk < 8; kk++) {
            int kb = kk * 16;
            uint32_t afr[2][4];
            #pragma unroll
            for (int mt = 0; mt < 2; mt++) {
                const __nv_bfloat16* base = pA + (mt * 16 + grp) * SM_STRIDE + kb + tig * 2;
                afr[mt][0] = *(const uint32_t*)(base);
                afr[mt][1] = *(const uint32_t*)(base + 8 * SM_STRIDE);
                afr[mt][2] = *(const uint32_t*)(base + 8);
                afr[mt][3] = *(const uint32_t*)(base + 8 * SM_STRIDE + 8);
            }
            uint32_t bfr[4][2];
            #pragma unroll
            for (int nt = 0; nt < 4; nt++) {
                const __nv_bfloat16* base = pB + (nt * 8 + grp) * SM_STRIDE + kb + tig * 2;
                bfr[nt][0] = *(const uint32_t*)(base);
                bfr[nt][1] = *(const uint32_t*)(base + 8);
            }
            #pragma unroll
            for (int mt = 0; mt < 2; mt++)
                #pragma unroll
                for (int nt = 0; nt < 4; nt++)
                    mma16816(acc[mt][nt], afr[mt], bfr[nt]);
        }

        // ---- epilogue: key = s - 0.5*sq_j -> score smem ----
        #pragma unroll
        for (int mt = 0; mt < 2; mt++) {
            #pragma unroll
            for (int nt = 0; nt < 4; nt++) {
                int lr = wm * 32 + mt * 16 + grp;
                int lc = wn * 32 + nt * 8 + tig * 2;
                int gc = t * 128 + lc;
                float h0 = 0.5f * sSQ[gc], h1 = 0.5f * sSQ[gc + 1];
                *(float2*)(sSc + lr * SC_STRIDE + lc) =
                    make_float2(acc[mt][nt][0] - h0, acc[mt][nt][1] - h1);
                *(float2*)(sSc + (lr + 8) * SC_STRIDE + lc) =
                    make_float2(acc[mt][nt][2] - h0, acc[mt][nt][3] - h1);
            }
        }
        __syncthreads();

        // ---- scan: thread (srow, seg) scans 32 cols of its row ----
        const float4* prow = (const float4*)(sSc + srow * SC_STRIDE + seg * 32);
        int jbase = t * 128 + seg * 32;
        #pragma unroll
        for (int i = 0; i < 8; i++) {
            float4 v = prow[i];
            int j = jbase + i * 4;
            if (v.x > bk[KNBR-1]) { float cv=v.x; int ci=j;
                #pragma unroll
                for (int s=0;s<KNBR;s++){ if(cv>bk[s]){float tf=bk[s];bk[s]=cv;cv=tf;int ti=bi[s];bi[s]=ci;ci=ti;} } }
            if (v.y > bk[KNBR-1]) { float cv=v.y; int ci=j+1;
                #pragma unroll
                for (int s=0;s<KNBR;s++){ if(cv>bk[s]){float tf=bk[s];bk[s]=cv;cv=tf;int ti=bi[s];bi[s]=ci;ci=ti;} } }
            if (v.z > bk[KNBR-1]) { float cv=v.z; int ci=j+2;
                #pragma unroll
                for (int s=0;s<KNBR;s++){ if(cv>bk[s]){float tf=bk[s];bk[s]=cv;cv=tf;int ti=bi[s];bi[s]=ci;ci=ti;} } }
            if (v.w > bk[KNBR-1]) { float cv=v.w; int ci=j+3;
                #pragma unroll
                for (int s=0;s<KNBR;s++){ if(cv>bk[s]){float tf=bk[s];bk[s]=cv;cv=tf;int ti=bi[s];bi[s]=ci;ci=ti;} } }
        }
        // next iter's top syncthreads separates this scan from next epilogue STS
    }

    // ---- final merge: 4 partial lists per row -> top-14 ----
    __syncthreads();
    float* stK = sSc;                       // staging reuses score smem (28.7 KB <= 33.8 KB)
    int*   stI = (int*)(sSc + 64 * 4 * KNBR);
    #pragma unroll
    for (int s = 0; s < KNBR; s++) {
        stK[(seg * 64 + srow) * KNBR + s] = bk[s];
        stI[(seg * 64 + srow) * KNBR + s] = bi[s];
    }
    __syncthreads();
    if (tid < 64) {
        float mk[KNBR]; int mi[KNBR];
        #pragma unroll
        for (int s = 0; s < KNBR; s++) { mk[s] = -3.4e38f; mi[s] = 0x7fffffff; }
        for (int sg = 0; sg < 4; sg++) {
            #pragma unroll
            for (int s = 0; s < KNBR; s++) {
                float cv = stK[(sg * 64 + tid) * KNBR + s];
                int   ci = stI[(sg * 64 + tid) * KNBR + s];
                if (cv > mk[KNBR-1] || (cv == mk[KNBR-1] && ci < mi[KNBR-1])) {
                    #pragma unroll
                    for (int s2 = 0; s2 < KNBR; s2++) {
                        if (cv > mk[s2] || (cv == mk[s2] && ci < mi[s2])) {
                            float tf = mk[s2]; mk[s2] = cv; cv = tf;
                            int   ti = mi[s2]; mi[s2] = ci; ci = ti;
                        }
                    }
                }
            }
        }
        #pragma unroll
        for (int s = 0; s < KNBR; s++) g_NBR[(rowBlk + tid) * KNBR + s] = mi[s];
    }
}

// ---------------- 3) bulk lo-dim loss: triangular (x2) ----------------
__global__ void bulk_kernel(const float* __restrict__ LO) {
    int ibase = blockIdx.x * 256, jbase = blockIdx.y * 512;
    if (jbase + 512 <= ibase) return;        // entirely below diagonal
    __shared__ float2 sLo[512];
    __shared__ double sred[256];
    int tid = threadIdx.x;
    const float2* lo2 = (const float2*)LO;
    int i = ibase + tid;
    float2 me = lo2[i];
    sLo[tid]       = lo2[jbase + tid];
    sLo[tid + 256] = lo2[jbase + 256 + tid];
    __syncthreads();

    float accf = 0.f;
    if (jbase >= ibase + 256) {              // interior: all j > i
        #pragma unroll 4
        for (int j = 0; j < 512; j++) {
            float2 o = sLo[j];
            float dx = me.x - o.x, dy = me.y - o.y;
            float d  = f_sqrt(fmaf(dx, dx, dy * dy));
            float r  = f_rcp(1.0f + d);
            accf += f_lg2((1.0f - r) + 1e-10f);
        }
        accf *= 2.0f;
    } else {                                 // boundary: per-element weight
        #pragma unroll 4
        for (int j = 0; j < 512; j++) {
            int jg = jbase + j;
            float2 o = sLo[j];
            float dx = me.x - o.x, dy = me.y - o.y;
            float d  = f_sqrt(fmaf(dx, dx, dy * dy));
            float r  = f_rcp(1.0f + d);
            float term = f_lg2((1.0f - r) + 1e-10f);
            float w = (jg > i) ? 2.0f : ((jg == i) ? 1.0f : 0.0f);
            accf += w * term;
        }
    }
    sred[tid] = (double)(accf * LN2F);
    __syncthreads();
    for (int off = 128; off; off >>= 1) { if (tid < off) sred[tid] += sred[tid + off]; __syncthreads(); }
    if (tid == 0) g_partial_bulk[blockIdx.y * 32 + blockIdx.x] = sred[0];
}

// ---------------- 4) exact neighbor correction ----------------
__global__ void corr_kernel(const float* __restrict__ X, const float* __restrict__ LO) {
    __shared__ double wsum[8];
    int warp = threadIdx.x >> 5, lane = threadIdx.x & 31;
    int row  = blockIdx.x * 8 + warp;
    const float* xi = X + (size_t)row * DIMS;
    float a0 = xi[lane], a1 = xi[lane + 32], a2 = xi[lane + 64], a3 = xi[lane + 96];
    const float2* lo2 = (const float2*)LO;
    float2 li = lo2[row];
    float sqi = g_SQ[row];

    float acc = 0.f;
    for (int n = 0; n < KNBR; n++) {
        int j = g_NBR[row * KNBR + n];
        const float* xj = X + (size_t)j * DIMS;
        float dot = a0 * xj[lane] + a1 * xj[lane + 32] + a2 * xj[lane + 64] + a3 * xj[lane + 96];
        #pragma unroll
        for (int off = 16; off; off >>= 1) dot += __shfl_xor_sync(0xffffffffu, dot, off);
        float d2h = fmaxf(sqi + g_SQ[j] - 2.f * dot, 0.f);
        float hd = f_sqrt(d2h);
        float hs = f_ex2(-LOG2EF * hd);
        float2 lj = lo2[j];
        float dx = li.x - lj.x, dy = li.y - lj.y;
        float ld = f_sqrt(fmaf(dx, dx, dy * dy));
        float r  = f_rcp(1.0f + ld);
        float A  = hs * (f_lg2(r + 1e-10f) * LN2F);
        float Bs = f_lg2((1.0f - r) + 1e-10f) * LN2F;   // matches bulk per-pair expression exactly
        acc += (A - Bs);
    }
    if (lane == 0) wsum[warp] = (double)acc;
    __syncthreads();
    if (threadIdx.x == 0) {
        double s = 0;
        for (int k = 0; k < 8; k++) s += wsum[k];
        g_partial_corr[blockIdx.x] = s;
    }
}

// ---------------- 5) deterministic final reduce ----------------
__global__ void final_kernel(float* __restrict__ out) {
    __shared__ double sred[256];
    int t = threadIdx.x;
    double s = 0;
    for (int k = t; k < 512;  k += 256) s += g_partial_bulk[k];
    for (int k = t; k < 1024; k += 256) s += g_partial_corr[k];
    sred[t] = s;
    __syncthreads();
    for (int off = 128; off; off >>= 1) { if (t < off) sred[t] += sred[t + off]; __syncthreads(); }
    if (t == 0) out[0] = (float)(-(sred[0] / 67108864.0) * 100.0);
}

// ---------------- launch ----------------
extern "C" void kernel_launch(void* const* d_in, const int* in_sizes, int n_in,
                              void* d_out, int out_size) {
    const float* X; const float* LO;
    if (in_sizes[0] == N_PTS * DIMS) { X = (const float*)d_in[0]; LO = (const float*)d_in[1]; }
    else                             { X = (const float*)d_in[1]; LO = (const float*)d_in[0]; }

    cudaFuncSetAttribute(fused_gemm_topk, cudaFuncAttributeMaxDynamicSharedMemorySize, SMEM_FUSED_TOTAL);

    prep_kernel    <<<N_PTS / 8, 256>>>(X);
    fused_gemm_topk<<<N_PTS / 64, 256, SMEM_FUSED_TOTAL>>>();
    bulk_kernel    <<<dim3(32, 16), 256>>>(LO);
    corr_kernel    <<<N_PTS / 8, 256>>>(X, LO);
    final_kernel   <<<1, 256>>>((float*)d_out);
}